// round 12
// baseline (speedup 1.0000x reference)
#include <cuda_runtime.h>
#include <cuda_bf16.h>
#include <cstdint>

// MK_MMDLoss R8: int8 IMMA Gram kernel (mma.sync m16n8k32 s8 -> s32).
//  - q = round(24*x) clamp +/-127 (clamp never fires for N(0,1) data);
//    dot_real = acc / 576. Quantization bias is common-mode across xx/yy/xy.
//  - K=256 int8 fully SMEM-resident (68KB) -> no chunk loop, 2 CTAs/SM.
//  - Diagonal excluded per-element, added analytically; norms fp32 exact.
//  - Finalize fused (ticket), shfl reduction.

#define NR    4096
#define CD    256
#define HWD   1024
#define BM    128
#define NTILE (NR / BM)     // 32
#define NSYM  (NTILE * (NTILE + 1) / 2)   // 528
#define NFULL (NTILE * NTILE)             // 1024
#define NBLK  (2 * NSYM + NFULL)          // 2080
#define ROWB  272            // smem row bytes: 256 + 16 pad (conflict-free ldmatrix)
#define ATILE (BM * ROWB)    // 34816
#define SM_RED (2 * ATILE)   // 69632
#define SM_TOT (SM_RED + 64)

#define QSCALE 24.0f
#define INVS2  (1.0f / (QSCALE * QSCALE))

__device__ __align__(16) int8_t g_xq[NR * CD];
__device__ __align__(16) int8_t g_yq[NR * CD];
__device__ float  g_x2[NR];
__device__ float  g_y2[NR];
__device__ double g_acc;
__device__ unsigned int g_done = 0;

__device__ __forceinline__ uint32_t smem_u32(const void* p) {
    uint32_t a;
    asm("{ .reg .u64 t; cvta.to.shared.u64 t, %1; cvt.u32.u64 %0, t; }" : "=r"(a) : "l"(p));
    return a;
}
__device__ __forceinline__ void cp16(uint32_t dst, const void* src) {
    asm volatile("cp.async.cg.shared.global [%0], [%1], 16;" :: "r"(dst), "l"(src));
}
__device__ __forceinline__ void cp_commit_wait() {
    asm volatile("cp.async.commit_group;");
    asm volatile("cp.async.wait_group 0;" ::: "memory");
}
__device__ __forceinline__ void ldsm4(uint32_t* d, uint32_t addr) {
    asm volatile("ldmatrix.sync.aligned.m8n8.x4.shared.b16 {%0,%1,%2,%3}, [%4];"
                 : "=r"(d[0]), "=r"(d[1]), "=r"(d[2]), "=r"(d[3]) : "r"(addr));
}
__device__ __forceinline__ void mma_s8(int* c, const uint32_t* a,
                                       uint32_t b0, uint32_t b1) {
    asm volatile(
        "mma.sync.aligned.m16n8k32.row.col.s32.s8.s8.s32 "
        "{%0,%1,%2,%3}, {%4,%5,%6,%7}, {%8,%9}, {%0,%1,%2,%3};"
        : "+r"(c[0]), "+r"(c[1]), "+r"(c[2]), "+r"(c[3])
        : "r"(a[0]), "r"(a[1]), "r"(a[2]), "r"(a[3]), "r"(b0), "r"(b1));
}

// ---------------- convert + transpose: (B,C,H,W) f32 -> [r][c] int8 ----------------
__global__ void mmd_convert_kernel(const float* __restrict__ x,
                                   const float* __restrict__ y) {
    __shared__ float tile[32][33];
    int hwb = blockIdx.x * 32;
    int cb  = blockIdx.y * 32;
    int z   = blockIdx.z;            // batch(4) x arr(2)
    int b   = z & 3;
    const float* src = (z >> 2) ? y : x;
    int8_t* dst = (z >> 2) ? g_yq : g_xq;
    int tx = threadIdx.x, ty = threadIdx.y;  // (32, 8)
    const float* s = src + (size_t)b * (CD * HWD) + hwb + tx;
#pragma unroll
    for (int i = 0; i < 4; ++i) {
        int c = cb + ty + i * 8;
        tile[ty + i * 8][tx] = s[(size_t)c * HWD];
    }
    __syncthreads();
#pragma unroll
    for (int i = 0; i < 4; ++i) {
        int hwl = ty + i * 8;
        int r = b * HWD + hwb + hwl;
        int v = __float2int_rn(QSCALE * tile[tx][hwl]);
        v = max(-127, min(127, v));
        dst[(size_t)r * CD + cb + tx] = (int8_t)v;
    }
}

// ---------------- row norms (fp32 from original data) ----------------
__global__ void mmd_norm_kernel(const float* __restrict__ x,
                                const float* __restrict__ y) {
    int r = blockIdx.x * blockDim.x + threadIdx.x;
    if (r == 0 && blockIdx.y == 0) g_acc = 0.0;
    const float* p = blockIdx.y ? y : x;
    int b  = r >> 10;
    int hw = r & 1023;
    const float* base = p + (size_t)b * (CD * HWD) + hw;
    float s = 0.f;
#pragma unroll 8
    for (int c = 0; c < CD; ++c) {
        float v = base[(size_t)c * HWD];
        s = fmaf(v, v, s);
    }
    (blockIdx.y ? g_y2 : g_x2)[r] = s;
}

// ---------------- merged main: 2080 blocks = xx(528) + yy(528) + xy(1024) ----------------
__global__ void __launch_bounds__(256, 2)
mmd_mma_kernel(const float* __restrict__ sig, float* __restrict__ out) {
    extern __shared__ __align__(128) char smem[];
    int tid = threadIdx.x, lane = tid & 31, wid = tid >> 5;

    int bidx = blockIdx.x;
    int mode, idx;
    if (bidx < NSYM)            { mode = 0; idx = bidx; }
    else if (bidx < 2 * NSYM)   { mode = 1; idx = bidx - NSYM; }
    else                        { mode = 2; idx = bidx - 2 * NSYM; }

    const int8_t *Ag, *Bg;
    const float *a2, *b2;
    double weight;
    int sym;
    if (mode == 0)      { Ag = g_xq; Bg = g_xq; a2 = g_x2; b2 = g_x2; weight =  1.0; sym = 1; }
    else if (mode == 1) { Ag = g_yq; Bg = g_yq; a2 = g_y2; b2 = g_y2; weight =  1.0; sym = 1; }
    else                { Ag = g_xq; Bg = g_yq; a2 = g_x2; b2 = g_y2; weight = -2.0; sym = 0; }

    int ti, tj;
    if (sym) {
        int b = idx; ti = 0;
        while (b >= NTILE - ti) { b -= NTILE - ti; ++ti; }
        tj = ti + b;
    } else {
        ti = idx / NTILE;
        tj = idx % NTILE;
    }
    int rowA0 = ti * BM, rowB0 = tj * BM;
    int diag_tile = (sym && ti == tj);

    uint32_t sb = smem_u32(smem);
    const int8_t* Abase = Ag + (size_t)rowA0 * CD;
    const int8_t* Bbase = Bg + (size_t)rowB0 * CD;

    // load whole K: A tile 128x256B = 2048 x 16B chunks, 8 per thread; same B.
    int lrow = tid >> 4, lch = tid & 15;   // base row 0..15, 16B-chunk 0..15
#pragma unroll
    for (int it = 0; it < 8; ++it) {
        int row = lrow + it * 16;
        cp16(sb + row * ROWB + lch * 16, Abase + (size_t)row * CD + lch * 16);
        if (!diag_tile)
            cp16(sb + ATILE + row * ROWB + lch * 16, Bbase + (size_t)row * CD + lch * 16);
    }
    cp_commit_wait();
    __syncthreads();

    // warp layout: 4x2 grid of 32(M) x 64(N) per warp
    int wm = wid >> 1, wn = wid & 1;
    uint32_t abase = sb + (uint32_t)(wm * 32 + (lane & 15)) * ROWB
                   + ((uint32_t)(lane >> 4) << 4);
    uint32_t bbase = sb + (diag_tile ? 0u : (uint32_t)ATILE)
                   + (uint32_t)(wn * 64 + (lane & 7) + ((lane >> 4) << 3)) * ROWB
                   + (((uint32_t)(lane >> 3) & 1) << 4);

    int acc[2][8][4];
#pragma unroll
    for (int i = 0; i < 2; ++i)
#pragma unroll
        for (int j = 0; j < 8; ++j)
#pragma unroll
            for (int e = 0; e < 4; ++e) acc[i][j][e] = 0;

#pragma unroll
    for (int ks = 0; ks < CD / 32; ++ks) {   // 8 k-steps of 32 int8
        uint32_t koff = (uint32_t)ks << 5;   // 32 bytes
        uint32_t a0[4], a1[4];
        ldsm4(a0, abase + koff);
        ldsm4(a1, abase + 16 * ROWB + koff);
#pragma unroll
        for (int ntp = 0; ntp < 4; ++ntp) {
            uint32_t bfr[4];
            ldsm4(bfr, bbase + (uint32_t)(ntp * 16) * ROWB + koff);
            mma_s8(acc[0][2 * ntp],     a0, bfr[0], bfr[1]);
            mma_s8(acc[0][2 * ntp + 1], a0, bfr[2], bfr[3]);
            mma_s8(acc[1][2 * ntp],     a1, bfr[0], bfr[1]);
            mma_s8(acc[1][2 * ntp + 1], a1, bfr[2], bfr[3]);
        }
    }

    // epilogue: d = a2 + b2 - 2*acc/576 ; 5-exp sum (exp skipped when t >= 30)
    float bet[5];
#pragma unroll
    for (int k = 0; k < 5; ++k) bet[k] = 0.5f / __ldg(&sig[k]);

    int g = lane >> 2, t4 = lane & 3;
    float part = 0.f;
#pragma unroll
    for (int mt = 0; mt < 2; ++mt) {
        int r0 = rowA0 + wm * 32 + mt * 16 + g;
        float a2lo = __ldg(a2 + r0);
        float a2hi = __ldg(a2 + r0 + 8);
#pragma unroll
        for (int nt = 0; nt < 8; ++nt) {
            int c0 = rowB0 + wn * 64 + nt * 8 + t4 * 2;
            float b2e[2] = { __ldg(b2 + c0), __ldg(b2 + c0 + 1) };
#pragma unroll
            for (int e = 0; e < 4; ++e) {
                int grow = (e < 2) ? r0 : r0 + 8;
                int gcol = c0 + (e & 1);
                if (diag_tile && grow == gcol) continue;  // diag added analytically
                float a2v = (e < 2) ? a2lo : a2hi;
                float d = fmaxf(fmaf(-2.0f * INVS2, (float)acc[mt][nt][e],
                                     a2v + b2e[e & 1]), 0.f);
                float s = 0.f;
#pragma unroll
                for (int k = 0; k < 5; ++k) {
                    float t = bet[k] * d;
                    if (t < 30.f) s += __expf(-t);
                }
                part += s;
            }
        }
    }
    if (sym && ti != tj) part *= 2.0f;

    // warp reduce + cross-warp
#pragma unroll
    for (int o = 16; o > 0; o >>= 1)
        part += __shfl_down_sync(0xFFFFFFFFu, part, o);
    float* sred = (float*)(smem + SM_RED);
    if (lane == 0) sred[wid] = part;
    __syncthreads();
    if (tid == 0) {
        float tot = 0.f;
#pragma unroll
        for (int w = 0; w < 8; ++w) tot += sred[w];
        atomicAdd(&g_acc, weight * (double)tot);
        __threadfence();
        unsigned int ticket = atomicAdd(&g_done, 1u);
        if (ticket == NBLK - 1) {
            g_done = 0;   // replay-safe reset
            // analytic diagonals of xx and yy: each row contributes 5
            out[0] = (float)((g_acc + 2.0 * 5.0 * (double)NR)
                             / ((double)NR * (double)NR));
        }
    }
}

extern "C" void kernel_launch(void* const* d_in, const int* in_sizes, int n_in,
                              void* d_out, int out_size) {
    const float* x   = (const float*)d_in[0];
    const float* y   = (const float*)d_in[1];
    const float* sig = (const float*)d_in[2];
    float* out = (float*)d_out;

    cudaFuncSetAttribute(mmd_mma_kernel,
                         cudaFuncAttributeMaxDynamicSharedMemorySize, SM_TOT);

    mmd_convert_kernel<<<dim3(HWD / 32, CD / 32, 8), dim3(32, 8)>>>(x, y);
    mmd_norm_kernel<<<dim3(NR / 256, 2), 256>>>(x, y);

    mmd_mma_kernel<<<NBLK, 256, SM_TOT>>>(sig, out);
}

// round 13
// speedup vs baseline: 1.3206x; 1.3206x over previous
#include <cuda_runtime.h>
#include <cuda_bf16.h>
#include <cstdint>

// MK_MMDLoss R12: R7 bf16 mma.sync mainloop (best: 121.6us) + overhauled
// epilogue: nested early-out exp2 chain (betas descending => passing set is a
// suffix), pre-negated log2e factors (1 FMUL + EX2 per exp), diag-specialized
// epilogue. int8 IMMA (R8) rejected: slower than bf16 on sm_103 fallback path.

#define NR    4096
#define CD    256
#define HWD   1024
#define BM    128
#define NTILE (NR / BM)     // 32
#define NSYM  (NTILE * (NTILE + 1) / 2)   // 528
#define NFULL (NTILE * NTILE)             // 1024
#define NBLK  (2 * NSYM + NFULL)          // 2080
#define KCH   64             // K chunk (bf16 elems)
#define NCHK  (CD / KCH)     // 4
#define ROWB  144            // smem row bytes: 128 + 16 pad (conflict-free ldmatrix)
#define ATILE (BM * ROWB)    // 18432
#define STG   (2 * ATILE)    // 36864 per stage (A+B)
#define SM_RED (2 * STG)     // 73728
#define SM_TOT (SM_RED + 64)

#define EXP2_CUT (-43.4f)    // == beta*d > ~30.1 -> term < 1e-13, dropped

__device__ __align__(16) __nv_bfloat16 g_xb[NR * CD];
__device__ __align__(16) __nv_bfloat16 g_yb[NR * CD];
__device__ float  g_x2[NR];
__device__ float  g_y2[NR];
__device__ double g_acc;
__device__ unsigned int g_done = 0;

__device__ __forceinline__ uint32_t smem_u32(const void* p) {
    uint32_t a;
    asm("{ .reg .u64 t; cvta.to.shared.u64 t, %1; cvt.u32.u64 %0, t; }" : "=r"(a) : "l"(p));
    return a;
}
__device__ __forceinline__ void cp16(uint32_t dst, const void* src) {
    asm volatile("cp.async.cg.shared.global [%0], [%1], 16;" :: "r"(dst), "l"(src));
}
__device__ __forceinline__ void cp_commit() {
    asm volatile("cp.async.commit_group;");
}
__device__ __forceinline__ void cp_wait1() {
    asm volatile("cp.async.wait_group 1;" ::: "memory");
}
__device__ __forceinline__ void cp_wait0() {
    asm volatile("cp.async.wait_group 0;" ::: "memory");
}
__device__ __forceinline__ void ldsm4(uint32_t* d, uint32_t addr) {
    asm volatile("ldmatrix.sync.aligned.m8n8.x4.shared.b16 {%0,%1,%2,%3}, [%4];"
                 : "=r"(d[0]), "=r"(d[1]), "=r"(d[2]), "=r"(d[3]) : "r"(addr));
}
__device__ __forceinline__ void mma_bf16(float* c, const uint32_t* a,
                                         uint32_t b0, uint32_t b1) {
    asm volatile(
        "mma.sync.aligned.m16n8k16.row.col.f32.bf16.bf16.f32 "
        "{%0,%1,%2,%3}, {%4,%5,%6,%7}, {%8,%9}, {%0,%1,%2,%3};"
        : "+f"(c[0]), "+f"(c[1]), "+f"(c[2]), "+f"(c[3])
        : "r"(a[0]), "r"(a[1]), "r"(a[2]), "r"(a[3]), "r"(b0), "r"(b1));
}

// 5-term Gaussian mix via nested early-out exp2 chain.
// nb[k] = -bet[k]*log2(e), bets descending -> passing set is suffix {k*..4}.
__device__ __forceinline__ float expmix(float d, const float* nb) {
    float s = exp2f(nb[4] * d);
    float u3 = nb[3] * d;
    if (u3 > EXP2_CUT) {
        s += exp2f(u3);
        float u2 = nb[2] * d;
        if (u2 > EXP2_CUT) {
            s += exp2f(u2);
            float u1 = nb[1] * d;
            if (u1 > EXP2_CUT) {
                s += exp2f(u1);
                float u0 = nb[0] * d;
                if (u0 > EXP2_CUT) s += exp2f(u0);
            }
        }
    }
    return s;
}

template <bool DIAG>
__device__ __forceinline__ float epilogue(const float acc[2][8][4],
                                          int rowA0, int rowB0, int wm, int wn,
                                          int lane, const float* a2,
                                          const float* b2, const float* nb) {
    int g = lane >> 2, t4 = lane & 3;
    float part = 0.f;
#pragma unroll
    for (int mt = 0; mt < 2; ++mt) {
        int r0 = rowA0 + wm * 32 + mt * 16 + g;
        float a2lo = __ldg(a2 + r0);
        float a2hi = __ldg(a2 + r0 + 8);
#pragma unroll
        for (int nt = 0; nt < 8; ++nt) {
            int c0 = rowB0 + wn * 64 + nt * 8 + t4 * 2;
            float b2e[2] = { __ldg(b2 + c0), __ldg(b2 + c0 + 1) };
#pragma unroll
            for (int e = 0; e < 4; ++e) {
                if (DIAG) {
                    int grow = (e < 2) ? r0 : r0 + 8;
                    int gcol = c0 + (e & 1);
                    if (grow == gcol) continue;   // diag added analytically
                }
                float a2v = (e < 2) ? a2lo : a2hi;
                float d = fmaxf(fmaf(-2.0f, acc[mt][nt][e], a2v + b2e[e & 1]), 0.f);
                part += expmix(d, nb);
            }
        }
    }
    return part;
}

// ---------------- convert + transpose: (B,C,H,W) f32 -> [r][c] bf16 ----------------
__global__ void mmd_convert_kernel(const float* __restrict__ x,
                                   const float* __restrict__ y) {
    __shared__ float tile[32][33];
    int hwb = blockIdx.x * 32;
    int cb  = blockIdx.y * 32;
    int z   = blockIdx.z;            // batch(4) x arr(2)
    int b   = z & 3;
    const float* src = (z >> 2) ? y : x;
    __nv_bfloat16* dst = (z >> 2) ? g_yb : g_xb;
    int tx = threadIdx.x, ty = threadIdx.y;  // (32, 8)
    const float* s = src + (size_t)b * (CD * HWD) + hwb + tx;
#pragma unroll
    for (int i = 0; i < 4; ++i) {
        int c = cb + ty + i * 8;
        tile[ty + i * 8][tx] = s[(size_t)c * HWD];
    }
    __syncthreads();
#pragma unroll
    for (int i = 0; i < 4; ++i) {
        int hwl = ty + i * 8;
        int r = b * HWD + hwb + hwl;
        dst[(size_t)r * CD + cb + tx] = __float2bfloat16(tile[tx][hwl]);
    }
}

// ---------------- row norms (fp32 from original data) ----------------
__global__ void mmd_norm_kernel(const float* __restrict__ x,
                                const float* __restrict__ y) {
    int r = blockIdx.x * blockDim.x + threadIdx.x;
    if (r == 0 && blockIdx.y == 0) g_acc = 0.0;
    const float* p = blockIdx.y ? y : x;
    int b  = r >> 10;
    int hw = r & 1023;
    const float* base = p + (size_t)b * (CD * HWD) + hw;
    float s = 0.f;
#pragma unroll 8
    for (int c = 0; c < CD; ++c) {
        float v = base[(size_t)c * HWD];
        s = fmaf(v, v, s);
    }
    (blockIdx.y ? g_y2 : g_x2)[r] = s;
}

// ---------------- merged main: 2080 blocks = xx(528) + yy(528) + xy(1024) ----------------
__global__ void __launch_bounds__(256, 2)
mmd_mma_kernel(const float* __restrict__ sig, float* __restrict__ out) {
    extern __shared__ __align__(128) char smem[];
    int tid = threadIdx.x, lane = tid & 31, wid = tid >> 5;

    int bidx = blockIdx.x;
    int mode, idx;
    if (bidx < NSYM)            { mode = 0; idx = bidx; }
    else if (bidx < 2 * NSYM)   { mode = 1; idx = bidx - NSYM; }
    else                        { mode = 2; idx = bidx - 2 * NSYM; }

    const __nv_bfloat16 *Ag, *Bg;
    const float *a2, *b2;
    double weight;
    int sym;
    if (mode == 0)      { Ag = g_xb; Bg = g_xb; a2 = g_x2; b2 = g_x2; weight =  1.0; sym = 1; }
    else if (mode == 1) { Ag = g_yb; Bg = g_yb; a2 = g_y2; b2 = g_y2; weight =  1.0; sym = 1; }
    else                { Ag = g_xb; Bg = g_yb; a2 = g_x2; b2 = g_y2; weight = -2.0; sym = 0; }

    int ti, tj;
    if (sym) {
        int b = idx; ti = 0;
        while (b >= NTILE - ti) { b -= NTILE - ti; ++ti; }
        tj = ti + b;
    } else {
        ti = idx / NTILE;
        tj = idx % NTILE;
    }
    int rowA0 = ti * BM, rowB0 = tj * BM;
    int diag_tile = (sym && ti == tj);

    uint32_t sb = smem_u32(smem);
    const __nv_bfloat16* Abase = Ag + (size_t)rowA0 * CD;
    const __nv_bfloat16* Bbase = Bg + (size_t)rowB0 * CD;

    // loader slots: 512 cp16 per matrix per chunk
    int lrow = tid >> 3, lch = tid & 7;   // base row 0..31, 16B-chunk 0..7

    // issue chunks 0 and 1
#pragma unroll
    for (int s = 0; s < 2; ++s) {
        uint32_t as = sb + s * STG, bs = as + ATILE;
#pragma unroll
        for (int it = 0; it < 4; ++it) {
            int row = lrow + it * 32;
            cp16(as + row * ROWB + lch * 16, Abase + (size_t)row * CD + s * KCH + lch * 8);
            cp16(bs + row * ROWB + lch * 16, Bbase + (size_t)row * CD + s * KCH + lch * 8);
        }
        cp_commit();
    }

    // warp layout: 4x2 grid of 32(M) x 64(N) per warp
    int wm = wid >> 1, wn = wid & 1;
    uint32_t arow = (uint32_t)(wm * 32 + (lane & 15)) * ROWB + ((uint32_t)(lane >> 4) << 4);
    uint32_t brow = (uint32_t)(wn * 64 + (lane & 7) + ((lane >> 4) << 3)) * ROWB
                  + (((uint32_t)(lane >> 3) & 1) << 4);

    float acc[2][8][4];
#pragma unroll
    for (int i = 0; i < 2; ++i)
#pragma unroll
        for (int j = 0; j < 8; ++j)
#pragma unroll
            for (int e = 0; e < 4; ++e) acc[i][j][e] = 0.f;

#pragma unroll
    for (int c = 0; c < NCHK; ++c) {
        if (c == NCHK - 1) cp_wait0(); else cp_wait1();
        __syncthreads();

        uint32_t abase = sb + (c & 1) * STG + arow;
        uint32_t bbase = sb + (c & 1) * STG + ATILE + brow;
#pragma unroll
        for (int ks = 0; ks < KCH / 16; ++ks) {
            uint32_t koff = (uint32_t)ks << 5;   // 16 bf16 = 32 bytes
            uint32_t a0[4], a1[4];
            ldsm4(a0, abase + koff);
            ldsm4(a1, abase + 16 * ROWB + koff);
#pragma unroll
            for (int ntp = 0; ntp < 4; ++ntp) {
                uint32_t bfr[4];
                ldsm4(bfr, bbase + (uint32_t)(ntp * 16) * ROWB + koff);
                mma_bf16(acc[0][2 * ntp],     a0, bfr[0], bfr[1]);
                mma_bf16(acc[0][2 * ntp + 1], a0, bfr[2], bfr[3]);
                mma_bf16(acc[1][2 * ntp],     a1, bfr[0], bfr[1]);
                mma_bf16(acc[1][2 * ntp + 1], a1, bfr[2], bfr[3]);
            }
        }
        __syncthreads();   // all reads of buf (c&1) done before refill

        if (c + 2 < NCHK) {
            int s = c & 1, ch = c + 2;
            uint32_t as = sb + s * STG, bs = as + ATILE;
#pragma unroll
            for (int it = 0; it < 4; ++it) {
                int row = lrow + it * 32;
                cp16(as + row * ROWB + lch * 16, Abase + (size_t)row * CD + ch * KCH + lch * 8);
                cp16(bs + row * ROWB + lch * 16, Bbase + (size_t)row * CD + ch * KCH + lch * 8);
            }
            cp_commit();
        }
    }

    // epilogue: nb[k] = -bet[k] * log2(e)
    float nb[5];
#pragma unroll
    for (int k = 0; k < 5; ++k)
        nb[k] = -1.4426950408889634f * (0.5f / __ldg(&sig[k]));

    float part = diag_tile
        ? epilogue<true >(acc, rowA0, rowB0, wm, wn, lane, a2, b2, nb)
        : epilogue<false>(acc, rowA0, rowB0, wm, wn, lane, a2, b2, nb);
    if (sym && ti != tj) part *= 2.0f;

    // warp reduce + cross-warp
#pragma unroll
    for (int o = 16; o > 0; o >>= 1)
        part += __shfl_down_sync(0xFFFFFFFFu, part, o);
    float* sred = (float*)(smem + SM_RED);
    if (lane == 0) sred[wid] = part;
    __syncthreads();
    if (tid == 0) {
        float tot = 0.f;
#pragma unroll
        for (int w = 0; w < 8; ++w) tot += sred[w];
        atomicAdd(&g_acc, weight * (double)tot);
        __threadfence();
        unsigned int ticket = atomicAdd(&g_done, 1u);
        if (ticket == NBLK - 1) {
            g_done = 0;   // replay-safe reset
            // analytic diagonals of xx and yy: each row contributes 5
            out[0] = (float)((g_acc + 2.0 * 5.0 * (double)NR)
                             / ((double)NR * (double)NR));
        }
    }
}

extern "C" void kernel_launch(void* const* d_in, const int* in_sizes, int n_in,
                              void* d_out, int out_size) {
    const float* x   = (const float*)d_in[0];
    const float* y   = (const float*)d_in[1];
    const float* sig = (const float*)d_in[2];
    float* out = (float*)d_out;

    cudaFuncSetAttribute(mmd_mma_kernel,
                         cudaFuncAttributeMaxDynamicSharedMemorySize, SM_TOT);

    mmd_convert_kernel<<<dim3(HWD / 32, CD / 32, 8), dim3(32, 8)>>>(x, y);
    mmd_norm_kernel<<<dim3(NR / 256, 2), 256>>>(x, y);

    mmd_mma_kernel<<<NBLK, 256, SM_TOT>>>(sig, out);
}

// round 15
// speedup vs baseline: 1.4257x; 1.0796x over previous
#include <cuda_runtime.h>
#include <cuda_bf16.h>
#include <cstdint>

// MK_MMDLoss R13: R12 + raised exp-drop threshold.
// EXP2_CUT -43.4 -> -24: terms < 2^-24 (~6e-8) dropped. Worst-case mean shift
// < 5e-7 (abs tol 2.4e-6), common-mode across xx/yy/xy. Typical entry now
// computes 1 exp2 instead of 2 and stops one guard earlier.

#define NR    4096
#define CD    256
#define HWD   1024
#define BM    128
#define NTILE (NR / BM)     // 32
#define NSYM  (NTILE * (NTILE + 1) / 2)   // 528
#define NFULL (NTILE * NTILE)             // 1024
#define NBLK  (2 * NSYM + NFULL)          // 2080
#define KCH   64             // K chunk (bf16 elems)
#define NCHK  (CD / KCH)     // 4
#define ROWB  144            // smem row bytes: 128 + 16 pad (conflict-free ldmatrix)
#define ATILE (BM * ROWB)    // 18432
#define STG   (2 * ATILE)    // 36864 per stage (A+B)
#define SM_RED (2 * STG)     // 73728
#define SM_TOT (SM_RED + 64)

#define EXP2_CUT (-24.0f)    // drop exp2 terms < 2^-24 ~ 6e-8 (see header note)

__device__ __align__(16) __nv_bfloat16 g_xb[NR * CD];
__device__ __align__(16) __nv_bfloat16 g_yb[NR * CD];
__device__ float  g_x2[NR];
__device__ float  g_y2[NR];
__device__ double g_acc;
__device__ unsigned int g_done = 0;

__device__ __forceinline__ uint32_t smem_u32(const void* p) {
    uint32_t a;
    asm("{ .reg .u64 t; cvta.to.shared.u64 t, %1; cvt.u32.u64 %0, t; }" : "=r"(a) : "l"(p));
    return a;
}
__device__ __forceinline__ void cp16(uint32_t dst, const void* src) {
    asm volatile("cp.async.cg.shared.global [%0], [%1], 16;" :: "r"(dst), "l"(src));
}
__device__ __forceinline__ void cp_commit() {
    asm volatile("cp.async.commit_group;");
}
__device__ __forceinline__ void cp_wait1() {
    asm volatile("cp.async.wait_group 1;" ::: "memory");
}
__device__ __forceinline__ void cp_wait0() {
    asm volatile("cp.async.wait_group 0;" ::: "memory");
}
__device__ __forceinline__ void ldsm4(uint32_t* d, uint32_t addr) {
    asm volatile("ldmatrix.sync.aligned.m8n8.x4.shared.b16 {%0,%1,%2,%3}, [%4];"
                 : "=r"(d[0]), "=r"(d[1]), "=r"(d[2]), "=r"(d[3]) : "r"(addr));
}
__device__ __forceinline__ void mma_bf16(float* c, const uint32_t* a,
                                         uint32_t b0, uint32_t b1) {
    asm volatile(
        "mma.sync.aligned.m16n8k16.row.col.f32.bf16.bf16.f32 "
        "{%0,%1,%2,%3}, {%4,%5,%6,%7}, {%8,%9}, {%0,%1,%2,%3};"
        : "+f"(c[0]), "+f"(c[1]), "+f"(c[2]), "+f"(c[3])
        : "r"(a[0]), "r"(a[1]), "r"(a[2]), "r"(a[3]), "r"(b0), "r"(b1));
}

// 5-term Gaussian mix via nested early-out exp2 chain.
// nb[k] = -bet[k]*log2(e), bets descending -> passing set is suffix {k*..4}.
__device__ __forceinline__ float expmix(float d, const float* nb) {
    float s = exp2f(nb[4] * d);
    float u3 = nb[3] * d;
    if (u3 > EXP2_CUT) {
        s += exp2f(u3);
        float u2 = nb[2] * d;
        if (u2 > EXP2_CUT) {
            s += exp2f(u2);
            float u1 = nb[1] * d;
            if (u1 > EXP2_CUT) {
                s += exp2f(u1);
                float u0 = nb[0] * d;
                if (u0 > EXP2_CUT) s += exp2f(u0);
            }
        }
    }
    return s;
}

template <bool DIAG>
__device__ __forceinline__ float epilogue(const float acc[2][8][4],
                                          int rowA0, int rowB0, int wm, int wn,
                                          int lane, const float* a2,
                                          const float* b2, const float* nb) {
    int g = lane >> 2, t4 = lane & 3;
    float part = 0.f;
#pragma unroll
    for (int mt = 0; mt < 2; ++mt) {
        int r0 = rowA0 + wm * 32 + mt * 16 + g;
        float a2lo = __ldg(a2 + r0);
        float a2hi = __ldg(a2 + r0 + 8);
#pragma unroll
        for (int nt = 0; nt < 8; ++nt) {
            int c0 = rowB0 + wn * 64 + nt * 8 + t4 * 2;
            float b2e[2] = { __ldg(b2 + c0), __ldg(b2 + c0 + 1) };
#pragma unroll
            for (int e = 0; e < 4; ++e) {
                if (DIAG) {
                    int grow = (e < 2) ? r0 : r0 + 8;
                    int gcol = c0 + (e & 1);
                    if (grow == gcol) continue;   // diag added analytically
                }
                float a2v = (e < 2) ? a2lo : a2hi;
                float d = fmaxf(fmaf(-2.0f, acc[mt][nt][e], a2v + b2e[e & 1]), 0.f);
                part += expmix(d, nb);
            }
        }
    }
    return part;
}

// ---------------- convert + transpose: (B,C,H,W) f32 -> [r][c] bf16 ----------------
__global__ void mmd_convert_kernel(const float* __restrict__ x,
                                   const float* __restrict__ y) {
    __shared__ float tile[32][33];
    int hwb = blockIdx.x * 32;
    int cb  = blockIdx.y * 32;
    int z   = blockIdx.z;            // batch(4) x arr(2)
    int b   = z & 3;
    const float* src = (z >> 2) ? y : x;
    __nv_bfloat16* dst = (z >> 2) ? g_yb : g_xb;
    int tx = threadIdx.x, ty = threadIdx.y;  // (32, 8)
    const float* s = src + (size_t)b * (CD * HWD) + hwb + tx;
#pragma unroll
    for (int i = 0; i < 4; ++i) {
        int c = cb + ty + i * 8;
        tile[ty + i * 8][tx] = s[(size_t)c * HWD];
    }
    __syncthreads();
#pragma unroll
    for (int i = 0; i < 4; ++i) {
        int hwl = ty + i * 8;
        int r = b * HWD + hwb + hwl;
        dst[(size_t)r * CD + cb + tx] = __float2bfloat16(tile[tx][hwl]);
    }
}

// ---------------- row norms (fp32 from original data) ----------------
__global__ void mmd_norm_kernel(const float* __restrict__ x,
                                const float* __restrict__ y) {
    int r = blockIdx.x * blockDim.x + threadIdx.x;
    if (r == 0 && blockIdx.y == 0) g_acc = 0.0;
    const float* p = blockIdx.y ? y : x;
    int b  = r >> 10;
    int hw = r & 1023;
    const float* base = p + (size_t)b * (CD * HWD) + hw;
    float s = 0.f;
#pragma unroll 8
    for (int c = 0; c < CD; ++c) {
        float v = base[(size_t)c * HWD];
        s = fmaf(v, v, s);
    }
    (blockIdx.y ? g_y2 : g_x2)[r] = s;
}

// ---------------- merged main: 2080 blocks = xx(528) + yy(528) + xy(1024) ----------------
__global__ void __launch_bounds__(256, 2)
mmd_mma_kernel(const float* __restrict__ sig, float* __restrict__ out) {
    extern __shared__ __align__(128) char smem[];
    int tid = threadIdx.x, lane = tid & 31, wid = tid >> 5;

    int bidx = blockIdx.x;
    int mode, idx;
    if (bidx < NSYM)            { mode = 0; idx = bidx; }
    else if (bidx < 2 * NSYM)   { mode = 1; idx = bidx - NSYM; }
    else                        { mode = 2; idx = bidx - 2 * NSYM; }

    const __nv_bfloat16 *Ag, *Bg;
    const float *a2, *b2;
    double weight;
    int sym;
    if (mode == 0)      { Ag = g_xb; Bg = g_xb; a2 = g_x2; b2 = g_x2; weight =  1.0; sym = 1; }
    else if (mode == 1) { Ag = g_yb; Bg = g_yb; a2 = g_y2; b2 = g_y2; weight =  1.0; sym = 1; }
    else                { Ag = g_xb; Bg = g_yb; a2 = g_x2; b2 = g_y2; weight = -2.0; sym = 0; }

    int ti, tj;
    if (sym) {
        int b = idx; ti = 0;
        while (b >= NTILE - ti) { b -= NTILE - ti; ++ti; }
        tj = ti + b;
    } else {
        ti = idx / NTILE;
        tj = idx % NTILE;
    }
    int rowA0 = ti * BM, rowB0 = tj * BM;
    int diag_tile = (sym && ti == tj);

    uint32_t sb = smem_u32(smem);
    const __nv_bfloat16* Abase = Ag + (size_t)rowA0 * CD;
    const __nv_bfloat16* Bbase = Bg + (size_t)rowB0 * CD;

    // loader slots: 512 cp16 per matrix per chunk
    int lrow = tid >> 3, lch = tid & 7;   // base row 0..31, 16B-chunk 0..7

    // issue chunks 0 and 1
#pragma unroll
    for (int s = 0; s < 2; ++s) {
        uint32_t as = sb + s * STG, bs = as + ATILE;
#pragma unroll
        for (int it = 0; it < 4; ++it) {
            int row = lrow + it * 32;
            cp16(as + row * ROWB + lch * 16, Abase + (size_t)row * CD + s * KCH + lch * 8);
            cp16(bs + row * ROWB + lch * 16, Bbase + (size_t)row * CD + s * KCH + lch * 8);
        }
        cp_commit();
    }

    // warp layout: 4x2 grid of 32(M) x 64(N) per warp
    int wm = wid >> 1, wn = wid & 1;
    uint32_t arow = (uint32_t)(wm * 32 + (lane & 15)) * ROWB + ((uint32_t)(lane >> 4) << 4);
    uint32_t brow = (uint32_t)(wn * 64 + (lane & 7) + ((lane >> 4) << 3)) * ROWB
                  + (((uint32_t)(lane >> 3) & 1) << 4);

    float acc[2][8][4];
#pragma unroll
    for (int i = 0; i < 2; ++i)
#pragma unroll
        for (int j = 0; j < 8; ++j)
#pragma unroll
            for (int e = 0; e < 4; ++e) acc[i][j][e] = 0.f;

#pragma unroll
    for (int c = 0; c < NCHK; ++c) {
        if (c == NCHK - 1) cp_wait0(); else cp_wait1();
        __syncthreads();

        uint32_t abase = sb + (c & 1) * STG + arow;
        uint32_t bbase = sb + (c & 1) * STG + ATILE + brow;
#pragma unroll
        for (int ks = 0; ks < KCH / 16; ++ks) {
            uint32_t koff = (uint32_t)ks << 5;   // 16 bf16 = 32 bytes
            uint32_t a0[4], a1[4];
            ldsm4(a0, abase + koff);
            ldsm4(a1, abase + 16 * ROWB + koff);
#pragma unroll
            for (int ntp = 0; ntp < 4; ++ntp) {
                uint32_t bfr[4];
                ldsm4(bfr, bbase + (uint32_t)(ntp * 16) * ROWB + koff);
                mma_bf16(acc[0][2 * ntp],     a0, bfr[0], bfr[1]);
                mma_bf16(acc[0][2 * ntp + 1], a0, bfr[2], bfr[3]);
                mma_bf16(acc[1][2 * ntp],     a1, bfr[0], bfr[1]);
                mma_bf16(acc[1][2 * ntp + 1], a1, bfr[2], bfr[3]);
            }
        }
        __syncthreads();   // all reads of buf (c&1) done before refill

        if (c + 2 < NCHK) {
            int s = c & 1, ch = c + 2;
            uint32_t as = sb + s * STG, bs = as + ATILE;
#pragma unroll
            for (int it = 0; it < 4; ++it) {
                int row = lrow + it * 32;
                cp16(as + row * ROWB + lch * 16, Abase + (size_t)row * CD + ch * KCH + lch * 8);
                cp16(bs + row * ROWB + lch * 16, Bbase + (size_t)row * CD + ch * KCH + lch * 8);
            }
            cp_commit();
        }
    }

    // epilogue: nb[k] = -bet[k] * log2(e)
    float nb[5];
#pragma unroll
    for (int k = 0; k < 5; ++k)
        nb[k] = -1.4426950408889634f * (0.5f / __ldg(&sig[k]));

    float part = diag_tile
        ? epilogue<true >(acc, rowA0, rowB0, wm, wn, lane, a2, b2, nb)
        : epilogue<false>(acc, rowA0, rowB0, wm, wn, lane, a2, b2, nb);
    if (sym && ti != tj) part *= 2.0f;

    // warp reduce + cross-warp
#pragma unroll
    for (int o = 16; o > 0; o >>= 1)
        part += __shfl_down_sync(0xFFFFFFFFu, part, o);
    float* sred = (float*)(smem + SM_RED);
    if (lane == 0) sred[wid] = part;
    __syncthreads();
    if (tid == 0) {
        float tot = 0.f;
#pragma unroll
        for (int w = 0; w < 8; ++w) tot += sred[w];
        atomicAdd(&g_acc, weight * (double)tot);
        __threadfence();
        unsigned int ticket = atomicAdd(&g_done, 1u);
        if (ticket == NBLK - 1) {
            g_done = 0;   // replay-safe reset
            // analytic diagonals of xx and yy: each row contributes 5
            out[0] = (float)((g_acc + 2.0 * 5.0 * (double)NR)
                             / ((double)NR * (double)NR));
        }
    }
}

extern "C" void kernel_launch(void* const* d_in, const int* in_sizes, int n_in,
                              void* d_out, int out_size) {
    const float* x   = (const float*)d_in[0];
    const float* y   = (const float*)d_in[1];
    const float* sig = (const float*)d_in[2];
    float* out = (float*)d_out;

    cudaFuncSetAttribute(mmd_mma_kernel,
                         cudaFuncAttributeMaxDynamicSharedMemorySize, SM_TOT);

    mmd_convert_kernel<<<dim3(HWD / 32, CD / 32, 8), dim3(32, 8)>>>(x, y);
    mmd_norm_kernel<<<dim3(NR / 256, 2), 256>>>(x, y);

    mmd_mma_kernel<<<NBLK, 256, SM_TOT>>>(sig, out);
}

// round 16
// speedup vs baseline: 1.6702x; 1.1715x over previous
#include <cuda_runtime.h>
#include <cuda_bf16.h>
#include <cstdint>

// MK_MMDLoss R15: R13 +
//  - convert & norm fused into one launch (independent jobs, z-plane split)
//  - 3-stage cp.async pipeline, ONE __syncthreads per chunk (was 2-stage/2)
//  - epilogue: exp2(u4)+exp2(u3) unconditional (EX2@-37 = 7e-12, harmless),
//    single rare guard at u2 -> removes per-entry divergence envelope.

#define NR    4096
#define CD    256
#define HWD   1024
#define BM    128
#define NTILE (NR / BM)     // 32
#define NSYM  (NTILE * (NTILE + 1) / 2)   // 528
#define NFULL (NTILE * NTILE)             // 1024
#define NBLK  (2 * NSYM + NFULL)          // 2080
#define KCH   64             // K chunk (bf16 elems)
#define NCHK  (CD / KCH)     // 4
#define NSTG  3              // pipeline stages
#define ROWB  144            // smem row bytes: 128 + 16 pad (conflict-free ldmatrix)
#define ATILE (BM * ROWB)    // 18432
#define STG   (2 * ATILE)    // 36864 per stage (A+B)
#define SM_RED (NSTG * STG)  // 110592
#define SM_TOT (SM_RED + 64)

#define EXP2_CUT (-24.0f)    // drop exp2 terms < 2^-24 ~ 6e-8

__device__ __align__(16) __nv_bfloat16 g_xb[NR * CD];
__device__ __align__(16) __nv_bfloat16 g_yb[NR * CD];
__device__ float  g_x2[NR];
__device__ float  g_y2[NR];
__device__ double g_acc;
__device__ unsigned int g_done = 0;

__device__ __forceinline__ uint32_t smem_u32(const void* p) {
    uint32_t a;
    asm("{ .reg .u64 t; cvta.to.shared.u64 t, %1; cvt.u32.u64 %0, t; }" : "=r"(a) : "l"(p));
    return a;
}
__device__ __forceinline__ void cp16(uint32_t dst, const void* src) {
    asm volatile("cp.async.cg.shared.global [%0], [%1], 16;" :: "r"(dst), "l"(src));
}
__device__ __forceinline__ void cp_commit() {
    asm volatile("cp.async.commit_group;");
}
__device__ __forceinline__ void cp_wait1() {
    asm volatile("cp.async.wait_group 1;" ::: "memory");
}
__device__ __forceinline__ void cp_wait0() {
    asm volatile("cp.async.wait_group 0;" ::: "memory");
}
__device__ __forceinline__ void ldsm4(uint32_t* d, uint32_t addr) {
    asm volatile("ldmatrix.sync.aligned.m8n8.x4.shared.b16 {%0,%1,%2,%3}, [%4];"
                 : "=r"(d[0]), "=r"(d[1]), "=r"(d[2]), "=r"(d[3]) : "r"(addr));
}
__device__ __forceinline__ void mma_bf16(float* c, const uint32_t* a,
                                         uint32_t b0, uint32_t b1) {
    asm volatile(
        "mma.sync.aligned.m16n8k16.row.col.f32.bf16.bf16.f32 "
        "{%0,%1,%2,%3}, {%4,%5,%6,%7}, {%8,%9}, {%0,%1,%2,%3};"
        : "+f"(c[0]), "+f"(c[1]), "+f"(c[2]), "+f"(c[3])
        : "r"(a[0]), "r"(a[1]), "r"(a[2]), "r"(a[3]), "r"(b0), "r"(b1));
}

// 5-term Gaussian mix. nb[k] = -bet[k]*log2(e), bets descending.
// u4/u3 terms computed unconditionally (EX2 handles tiny args natively);
// terms 0..2 behind one rarely-taken guard.
__device__ __forceinline__ float expmix(float d, const float* nb) {
    float s = exp2f(nb[4] * d) + exp2f(nb[3] * d);
    float u2 = nb[2] * d;
    if (u2 > EXP2_CUT) {
        s += exp2f(u2);
        float u1 = nb[1] * d;
        if (u1 > EXP2_CUT) {
            s += exp2f(u1);
            float u0 = nb[0] * d;
            if (u0 > EXP2_CUT) s += exp2f(u0);
        }
    }
    return s;
}

template <bool DIAG>
__device__ __forceinline__ float epilogue(const float acc[2][8][4],
                                          int rowA0, int rowB0, int wm, int wn,
                                          int lane, const float* a2,
                                          const float* b2, const float* nb) {
    int g = lane >> 2, t4 = lane & 3;
    float part = 0.f;
#pragma unroll
    for (int mt = 0; mt < 2; ++mt) {
        int r0 = rowA0 + wm * 32 + mt * 16 + g;
        float a2lo = __ldg(a2 + r0);
        float a2hi = __ldg(a2 + r0 + 8);
#pragma unroll
        for (int nt = 0; nt < 8; ++nt) {
            int c0 = rowB0 + wn * 64 + nt * 8 + t4 * 2;
            float b2e[2] = { __ldg(b2 + c0), __ldg(b2 + c0 + 1) };
#pragma unroll
            for (int e = 0; e < 4; ++e) {
                if (DIAG) {
                    int grow = (e < 2) ? r0 : r0 + 8;
                    int gcol = c0 + (e & 1);
                    if (grow == gcol) continue;   // diag added analytically
                }
                float a2v = (e < 2) ? a2lo : a2hi;
                float d = fmaxf(fmaf(-2.0f, acc[mt][nt][e], a2v + b2e[e & 1]), 0.f);
                part += expmix(d, nb);
            }
        }
    }
    return part;
}

// ---------------- fused prep: convert (z<8) + row norms (z==8) ----------------
__global__ void mmd_prep_kernel(const float* __restrict__ x,
                                const float* __restrict__ y) {
    __shared__ float tile[32][33];
    int tx = threadIdx.x, ty = threadIdx.y;  // (32, 8)
    int tid = ty * 32 + tx;
    int z = blockIdx.z;

    if (z == 8) {
        // norm job: 32 x-blocks (y==0) cover both arrays; others no-op
        if (blockIdx.y != 0) return;
        int r = blockIdx.x * 256 + tid;      // 0..8191
        if (r == 0) g_acc = 0.0;
        int arr = r >> 12;
        int row = r & 4095;
        const float* p = arr ? y : x;
        int b  = row >> 10;
        int hw = row & 1023;
        const float* base = p + (size_t)b * (CD * HWD) + hw;
        float s = 0.f;
#pragma unroll 8
        for (int c = 0; c < CD; ++c) {
            float v = base[(size_t)c * HWD];
            s = fmaf(v, v, s);
        }
        (arr ? g_y2 : g_x2)[row] = s;
        return;
    }

    // convert job: (B,C,H,W) f32 -> [r][c] bf16
    int hwb = blockIdx.x * 32;
    int cb  = blockIdx.y * 32;
    int b   = z & 3;
    const float* src = (z >> 2) ? y : x;
    __nv_bfloat16* dst = (z >> 2) ? g_yb : g_xb;
    const float* s = src + (size_t)b * (CD * HWD) + hwb + tx;
#pragma unroll
    for (int i = 0; i < 4; ++i) {
        int c = cb + ty + i * 8;
        tile[ty + i * 8][tx] = s[(size_t)c * HWD];
    }
    __syncthreads();
#pragma unroll
    for (int i = 0; i < 4; ++i) {
        int hwl = ty + i * 8;
        int r = b * HWD + hwb + hwl;
        dst[(size_t)r * CD + cb + tx] = __float2bfloat16(tile[tx][hwl]);
    }
}

// ---------------- merged main: 2080 blocks = xx(528) + yy(528) + xy(1024) ----------------
__global__ void __launch_bounds__(256, 2)
mmd_mma_kernel(const float* __restrict__ sig, float* __restrict__ out) {
    extern __shared__ __align__(128) char smem[];
    int tid = threadIdx.x, lane = tid & 31, wid = tid >> 5;

    int bidx = blockIdx.x;
    int mode, idx;
    if (bidx < NSYM)            { mode = 0; idx = bidx; }
    else if (bidx < 2 * NSYM)   { mode = 1; idx = bidx - NSYM; }
    else                        { mode = 2; idx = bidx - 2 * NSYM; }

    const __nv_bfloat16 *Ag, *Bg;
    const float *a2, *b2;
    double weight;
    int sym;
    if (mode == 0)      { Ag = g_xb; Bg = g_xb; a2 = g_x2; b2 = g_x2; weight =  1.0; sym = 1; }
    else if (mode == 1) { Ag = g_yb; Bg = g_yb; a2 = g_y2; b2 = g_y2; weight =  1.0; sym = 1; }
    else                { Ag = g_xb; Bg = g_yb; a2 = g_x2; b2 = g_y2; weight = -2.0; sym = 0; }

    int ti, tj;
    if (sym) {
        int b = idx; ti = 0;
        while (b >= NTILE - ti) { b -= NTILE - ti; ++ti; }
        tj = ti + b;
    } else {
        ti = idx / NTILE;
        tj = idx % NTILE;
    }
    int rowA0 = ti * BM, rowB0 = tj * BM;
    int diag_tile = (sym && ti == tj);

    uint32_t sb = smem_u32(smem);
    const __nv_bfloat16* Abase = Ag + (size_t)rowA0 * CD;
    const __nv_bfloat16* Bbase = Bg + (size_t)rowB0 * CD;

    // loader slots: 512 cp16 per matrix per chunk
    int lrow = tid >> 3, lch = tid & 7;   // base row 0..31, 16B-chunk 0..7

    // prologue: issue chunks 0 and 1 into stages 0 and 1
#pragma unroll
    for (int s = 0; s < 2; ++s) {
        uint32_t as = sb + s * STG, bs = as + ATILE;
#pragma unroll
        for (int it = 0; it < 4; ++it) {
            int row = lrow + it * 32;
            cp16(as + row * ROWB + lch * 16, Abase + (size_t)row * CD + s * KCH + lch * 8);
            cp16(bs + row * ROWB + lch * 16, Bbase + (size_t)row * CD + s * KCH + lch * 8);
        }
        cp_commit();
    }

    // warp layout: 4x2 grid of 32(M) x 64(N) per warp
    int wm = wid >> 1, wn = wid & 1;
    uint32_t arow = (uint32_t)(wm * 32 + (lane & 15)) * ROWB + ((uint32_t)(lane >> 4) << 4);
    uint32_t brow = (uint32_t)(wn * 64 + (lane & 7) + ((lane >> 4) << 3)) * ROWB
                  + (((uint32_t)(lane >> 3) & 1) << 4);

    float acc[2][8][4];
#pragma unroll
    for (int i = 0; i < 2; ++i)
#pragma unroll
        for (int j = 0; j < 8; ++j)
#pragma unroll
            for (int e = 0; e < 4; ++e) acc[i][j][e] = 0.f;

    // 3-stage pipeline, ONE sync per chunk.
    // Top-of-iter sync also guarantees stage (c+2)%3's old readers (iter c-1)
    // are done before the refill issued later this iter.
#pragma unroll
    for (int c = 0; c < NCHK; ++c) {
        if (c < NCHK - 1) cp_wait1(); else cp_wait0();
        __syncthreads();

        uint32_t abase = sb + (c % NSTG) * STG + arow;
        uint32_t bbase = sb + (c % NSTG) * STG + ATILE + brow;
#pragma unroll
        for (int ks = 0; ks < KCH / 16; ++ks) {
            uint32_t koff = (uint32_t)ks << 5;   // 16 bf16 = 32 bytes
            uint32_t a0[4], a1[4];
            ldsm4(a0, abase + koff);
            ldsm4(a1, abase + 16 * ROWB + koff);
#pragma unroll
            for (int ntp = 0; ntp < 4; ++ntp) {
                uint32_t bfr[4];
                ldsm4(bfr, bbase + (uint32_t)(ntp * 16) * ROWB + koff);
                mma_bf16(acc[0][2 * ntp],     a0, bfr[0], bfr[1]);
                mma_bf16(acc[0][2 * ntp + 1], a0, bfr[2], bfr[3]);
                mma_bf16(acc[1][2 * ntp],     a1, bfr[0], bfr[1]);
                mma_bf16(acc[1][2 * ntp + 1], a1, bfr[2], bfr[3]);
            }
        }

        if (c + 2 < NCHK) {
            int ch = c + 2;
            uint32_t as = sb + (ch % NSTG) * STG, bs = as + ATILE;
#pragma unroll
            for (int it = 0; it < 4; ++it) {
                int row = lrow + it * 32;
                cp16(as + row * ROWB + lch * 16, Abase + (size_t)row * CD + ch * KCH + lch * 8);
                cp16(bs + row * ROWB + lch * 16, Bbase + (size_t)row * CD + ch * KCH + lch * 8);
            }
            cp_commit();
        }
    }

    // epilogue: nb[k] = -bet[k] * log2(e)
    float nb[5];
#pragma unroll
    for (int k = 0; k < 5; ++k)
        nb[k] = -1.4426950408889634f * (0.5f / __ldg(&sig[k]));

    float part = diag_tile
        ? epilogue<true >(acc, rowA0, rowB0, wm, wn, lane, a2, b2, nb)
        : epilogue<false>(acc, rowA0, rowB0, wm, wn, lane, a2, b2, nb);
    if (sym && ti != tj) part *= 2.0f;

    // warp reduce + cross-warp
#pragma unroll
    for (int o = 16; o > 0; o >>= 1)
        part += __shfl_down_sync(0xFFFFFFFFu, part, o);
    float* sred = (float*)(smem + SM_RED);
    if (lane == 0) sred[wid] = part;
    __syncthreads();
    if (tid == 0) {
        float tot = 0.f;
#pragma unroll
        for (int w = 0; w < 8; ++w) tot += sred[w];
        atomicAdd(&g_acc, weight * (double)tot);
        __threadfence();
        unsigned int ticket = atomicAdd(&g_done, 1u);
        if (ticket == NBLK - 1) {
            g_done = 0;   // replay-safe reset
            // analytic diagonals of xx and yy: each row contributes 5
            out[0] = (float)((g_acc + 2.0 * 5.0 * (double)NR)
                             / ((double)NR * (double)NR));
        }
    }
}

extern "C" void kernel_launch(void* const* d_in, const int* in_sizes, int n_in,
                              void* d_out, int out_size) {
    const float* x   = (const float*)d_in[0];
    const float* y   = (const float*)d_in[1];
    const float* sig = (const float*)d_in[2];
    float* out = (float*)d_out;

    cudaFuncSetAttribute(mmd_mma_kernel,
                         cudaFuncAttributeMaxDynamicSharedMemorySize, SM_TOT);

    mmd_prep_kernel<<<dim3(HWD / 32, CD / 32, 9), dim3(32, 8)>>>(x, y);
    mmd_mma_kernel<<<NBLK, 256, SM_TOT>>>(sig, out);
}